// round 17
// baseline (speedup 1.0000x reference)
#include <cuda_runtime.h>
#include <cuda_fp16.h>
#include <cuda_bf16.h>

#define NN 100000
#define EE 1000000
#define HH 64
#define GG 512
#define BN_EPS 1e-5f

#define SCAN_B 1024
#define NBLK ((NN + SCAN_B - 1) / SCAN_B)   // 98

typedef unsigned long long ull;

// ---------------- device scratch (no allocations allowed) ----------------
__device__ __align__(16) __half g_hl16[NN * HH]; // lin output (fp16 payload, NOT dinv-scaled)
__device__ __align__(16) float  g_out[NN * HH];  // relu(agg+bias) raw layer output
__device__ float g_dinv[NN];
__device__ int   g_edeg[NN];        // edge-only in-degree
__device__ int   g_off [NN + 1];    // CSR offsets
__device__ int   g_cur [NN];        // bucket cursors
__device__ int   g_esrc[EE];        // src index bucketed by dst
__device__ int   g_part[NBLK];      // scan partials
__device__ int   g_cnt [GG];
__device__ float g_sum  [3 * HH];   // per-layer raw relu sums (BN stats)
__device__ float g_sumsq[3 * HH];

// ---------------- helpers ----------------
__device__ __forceinline__ ull fma2(ull a, ull b, ull c) {
    ull d;
    asm("fma.rn.f32x2 %0, %1, %2, %3;" : "=l"(d) : "l"(a), "l"(b), "l"(c));
    return d;
}
__device__ __forceinline__ ull dup2(float x) {
    ull d;
    unsigned r = __float_as_uint(x);
    asm("mov.b64 %0, {%1, %1};" : "=l"(d) : "r"(r));
    return d;
}
__device__ __forceinline__ ull pk2(float a, float b) {
    ull d;
    asm("mov.b64 %0, {%1, %2};" : "=l"(d)
        : "r"(__float_as_uint(a)), "r"(__float_as_uint(b)));
    return d;
}
__device__ __forceinline__ float2 unp2(ull a) {
    unsigned lo, hi;
    asm("mov.b64 {%0, %1}, %2;" : "=r"(lo), "=r"(hi) : "l"(a));
    return make_float2(__uint_as_float(lo), __uint_as_float(hi));
}
__device__ __forceinline__ float4 h4f4(uint2 u) {
    __half2 a = *reinterpret_cast<__half2*>(&u.x);
    __half2 b = *reinterpret_cast<__half2*>(&u.y);
    float2 fa = __half22float2(a), fb = __half22float2(b);
    return make_float4(fa.x, fa.y, fb.x, fb.y);
}
__device__ __forceinline__ void pdl_wait() { cudaGridDependencySynchronize(); }

// ---------------- init ----------------
__global__ void k_init(float* __restrict__ dout)
{
    int i = blockIdx.x * blockDim.x + threadIdx.x;
    if (i < NN)            g_edeg[i] = 0;
    if (i < GG * 3 * HH)   dout[i]  = 0.0f;       // pooled region
    if (i < 3 * HH) { g_sum[i] = 0.0f; g_sumsq[i] = 0.0f; }
    if (i < GG)       g_cnt[i] = 0;
}

// ---------------- edge-only in-degree over dst (4 edges/thread) ----------
__global__ void k_deg(const int* __restrict__ dst)
{
    int t = blockIdx.x * blockDim.x + threadIdx.x;
    if (t >= EE / 4) return;
    pdl_wait();
    int4 d = ((const int4*)dst)[t];
    atomicAdd(&g_edeg[d.x], 1);
    atomicAdd(&g_edeg[d.y], 1);
    atomicAdd(&g_edeg[d.z], 1);
    atomicAdd(&g_edeg[d.w], 1);
}

// ---------------- exclusive scan of g_edeg -> g_off ----------------------
__global__ __launch_bounds__(SCAN_B) void k_scan1()
{
    __shared__ int sh[SCAN_B];
    int t = threadIdx.x;
    int i = blockIdx.x * SCAN_B + t;
    pdl_wait();
    int v = (i < NN) ? g_edeg[i] : 0;
    sh[t] = v;
    __syncthreads();
    int val = v;
    for (int d = 1; d < SCAN_B; d <<= 1) {
        int add = (t >= d) ? sh[t - d] : 0;
        __syncthreads();
        val += add;
        sh[t] = val;
        __syncthreads();
    }
    if (i < NN) g_off[i] = val - v;                // local exclusive
    if (t == SCAN_B - 1) g_part[blockIdx.x] = val; // block total
}

// scan finalize (per-block redundant scan of 98 partials) + dinv + counts
__global__ __launch_bounds__(256) void k_scan3(const int* __restrict__ batch)
{
    __shared__ int ws[4];
    __shared__ int sExcl[128];
    int t = threadIdx.x;            // 256
    pdl_wait();
    if (t < 128) {
        int v = (t < NBLK) ? g_part[t] : 0;
        int lane = t & 31, w = t >> 5;
        int inc = v;
#pragma unroll
        for (int d = 1; d < 32; d <<= 1) {
            int n = __shfl_up_sync(0xFFFFFFFFu, inc, d);
            if (lane >= d) inc += n;
        }
        if (lane == 31) ws[w] = inc;
        sExcl[t] = inc - v;
    }
    __syncthreads();
    if (t < 128) {
        int w = t >> 5;
        int base = 0;
        for (int j = 0; j < w; j++) base += ws[j];
        sExcl[t] += base;
    }
    __syncthreads();

    int i = blockIdx.x * 256 + t;
    if (i < NN) {
        int o = g_off[i] + sExcl[i / SCAN_B];
        g_off[i] = o;
        g_cur[i] = o;
        g_dinv[i] = rsqrtf((float)(g_edeg[i] + 1));   // +1 self loop
    }
    if (i == 0) g_off[NN] = EE;

    int start = i * 16;
    if (start < NN) {
        int end = min(start + 16, NN);
        int curg = batch[start], acc = 0;
        for (int n = start; n < end; n++) {
            int gi = batch[n];
            if (gi != curg) { atomicAdd(&g_cnt[curg], acc); curg = gi; acc = 0; }
            acc++;
        }
        atomicAdd(&g_cnt[curg], acc);
    }
}

// ---------------- bucket edges by dst (4 edges/thread) -------------------
__global__ void k_bucket(const int* __restrict__ src, const int* __restrict__ dst)
{
    int t = blockIdx.x * blockDim.x + threadIdx.x;
    if (t >= EE / 4) return;
    pdl_wait();
    int4 s = ((const int4*)src)[t];
    int4 d = ((const int4*)dst)[t];
    int p0 = atomicAdd(&g_cur[d.x], 1);
    int p1 = atomicAdd(&g_cur[d.y], 1);
    int p2 = atomicAdd(&g_cur[d.z], 1);
    int p3 = atomicAdd(&g_cur[d.w], 1);
    g_esrc[p0] = s.x;
    g_esrc[p1] = s.y;
    g_esrc[p2] = s.z;
    g_esrc[p3] = s.w;
}

// ---------------- fused BN + GEMM: HL = (sc*X + dc) @ W^T ----------------
// BN params of the PREVIOUS layer computed in-prologue from g_sum/g_sumsq
// (gam==nullptr -> identity, layer 0). Writes g_hl16 (fp16).
__global__ __launch_bounds__(128) void k_gemm(const float* __restrict__ X,
                                              const float* __restrict__ W,
                                              const float* __restrict__ gam,
                                              const float* __restrict__ bet,
                                              int statsLayer)
{
    __shared__ __align__(16) float  sW[HH * HH];   // sW[k*64+o] = W[o][k] (raw, then *sc[k])
    __shared__ float4 sX[128 * 17];
    __shared__ __align__(16) float sSc[HH], sDc[HH], sCv[HH];
    int tid  = threadIdx.x;
    int base = blockIdx.x * 128;

    // stage raw W^T into smem — W is a constant input, safe before pdl_wait
    for (int i = tid; i < HH * HH; i += 128) {
        int o = i >> 6, k = i & 63;
        sW[k * HH + o] = W[i];
    }

    pdl_wait();   // g_sum/g_sumsq from k_agg; X = g_out from k_agg

    if (tid < HH) {
        float sc = 1.f, dc = 0.f;
        if (gam) {
            float m   = g_sum  [statsLayer * HH + tid] * (1.0f / NN);
            float var = g_sumsq[statsLayer * HH + tid] * (1.0f / NN) - m * m;
            float r = rsqrtf(var + BN_EPS);
            sc = gam[tid] * r;
            dc = bet[tid] - m * sc;
        }
        sSc[tid] = sc;
        sDc[tid] = dc;
    }
    __syncthreads();

    // scale sW in place: linear idx i = k*64+o  ->  k = i>>6
    for (int i = tid; i < HH * HH; i += 128) sW[i] *= sSc[i >> 6];
    // cvec[o] = sum_k dc[k] * W[o][k]  (from global W, rows are coalesced/L1-hot)
    if (tid < HH) {
        float a = 0.f;
#pragma unroll 8
        for (int k = 0; k < HH; k++) a = fmaf(sDc[k], W[tid * HH + k], a);
        sCv[tid] = a;
    }
    for (int i = tid; i < 128 * 16; i += 128) {
        int r = i >> 4, c4 = i & 15;
        int node = base + r;
        float4 v = make_float4(0.f, 0.f, 0.f, 0.f);
        if (node < NN) v = ((const float4*)X)[(size_t)node * 16 + c4];
        sX[r * 17 + c4] = v;
    }
    __syncthreads();

    int oh = tid & 1;
    int pn = tid >> 1;
    int n0 = base + pn, n1 = base + 64 + pn;

    ull a0[16], a1[16];
#pragma unroll
    for (int j = 0; j < 8; j++) {
        float2 c0 = *(float2*)&sCv[oh * 32 + 4 * j];
        float2 c1 = *(float2*)&sCv[oh * 32 + 4 * j + 2];
        ull p0 = pk2(c0.x, c0.y), p1 = pk2(c1.x, c1.y);
        a0[2*j] = p0; a0[2*j+1] = p1;
        a1[2*j] = p0; a1[2*j+1] = p1;
    }

#pragma unroll 4
    for (int k4 = 0; k4 < 16; k4++) {
        float4 xv0 = sX[pn * 17 + k4];
        float4 xv1 = sX[(pn + 64) * 17 + k4];
#pragma unroll
        for (int kk = 0; kk < 4; kk++) {
            float xs0 = (kk == 0) ? xv0.x : (kk == 1) ? xv0.y : (kk == 2) ? xv0.z : xv0.w;
            float xs1 = (kk == 0) ? xv1.x : (kk == 1) ? xv1.y : (kk == 2) ? xv1.z : xv1.w;
            ull xx0 = dup2(xs0);
            ull xx1 = dup2(xs1);
            const ulonglong2* wr = (const ulonglong2*)(sW + (k4 * 4 + kk) * HH + oh * 32);
#pragma unroll
            for (int j = 0; j < 8; j++) {
                ulonglong2 w = wr[j];
                a0[2*j]   = fma2(xx0, w.x, a0[2*j]);
                a0[2*j+1] = fma2(xx0, w.y, a0[2*j+1]);
                a1[2*j]   = fma2(xx1, w.x, a1[2*j]);
                a1[2*j+1] = fma2(xx1, w.y, a1[2*j+1]);
            }
        }
    }

    if (n0 < NN) {
        uint2* hl = (uint2*)(g_hl16 + (size_t)n0 * HH + oh * 32);
#pragma unroll
        for (int j = 0; j < 8; j++) {
            float2 lo = unp2(a0[2*j]), hi = unp2(a0[2*j+1]);
            __half2 h0 = __float22half2_rn(lo);
            __half2 h1 = __float22half2_rn(hi);
            hl[j] = make_uint2(*(unsigned*)&h0, *(unsigned*)&h1);
        }
    }
    if (n1 < NN) {
        uint2* hl = (uint2*)(g_hl16 + (size_t)n1 * HH + oh * 32);
#pragma unroll
        for (int j = 0; j < 8; j++) {
            float2 lo = unp2(a1[2*j]), hi = unp2(a1[2*j+1]);
            __half2 h0 = __float22half2_rn(lo);
            __half2 h1 = __float22half2_rn(hi);
            hl[j] = make_uint2(*(unsigned*)&h0, *(unsigned*)&h1);
        }
    }
}

// ---- fused pull-aggregate + bias + relu + BN stats + raw segment pool ----
__global__ __launch_bounds__(256) void k_agg(const float* __restrict__ b,
                                             const int* __restrict__ batch,
                                             float* __restrict__ pool, int layer)
{
    int tid = threadIdx.x;
    int grp = tid >> 4;
    int q   = tid & 15;
    int node = blockIdx.x * 16 + grp;      // grid is exactly NN/16

    unsigned mask = 0xFFFFu << (((tid & 31) >> 4) << 4);

    pdl_wait();   // g_hl16 from k_gemm

    const uint2* hl2 = (const uint2*)g_hl16;   // 8B = 4 halves per element
    float di = g_dinv[node];
    float4 vs = h4f4(hl2[(size_t)node * 16 + q]);
    float4 acc = make_float4(vs.x * di, vs.y * di, vs.z * di, vs.w * di);

    int beg = g_off[node], end = g_off[node + 1];
    for (int p = beg; p < end; p += 16) {
        int rem = end - p;                                  // group-uniform
        int idx = (q < rem) ? g_esrc[p + q] : 0;
        float dsl = g_dinv[idx];

        uint2 v[8];
        float w[8];
#pragma unroll
        for (int j = 0; j < 8; j++) {
            int s = __shfl_sync(mask, idx, j, 16);
            w[j]  = __shfl_sync(mask, dsl, j, 16);
            v[j]  = hl2[(size_t)s * 16 + q];
        }
#pragma unroll
        for (int j = 0; j < 8; j++) {
            if (j < rem) {
                float4 f = h4f4(v[j]);
                acc.x = fmaf(f.x, w[j], acc.x);
                acc.y = fmaf(f.y, w[j], acc.y);
                acc.z = fmaf(f.z, w[j], acc.z);
                acc.w = fmaf(f.w, w[j], acc.w);
            }
        }
        if (rem > 8) {
#pragma unroll
            for (int j = 0; j < 8; j++) {
                int s = __shfl_sync(mask, idx, 8 + j, 16);
                w[j]  = __shfl_sync(mask, dsl, 8 + j, 16);
                v[j]  = hl2[(size_t)s * 16 + q];
            }
#pragma unroll
            for (int j = 0; j < 8; j++) {
                if (8 + j < rem) {
                    float4 f = h4f4(v[j]);
                    acc.x = fmaf(f.x, w[j], acc.x);
                    acc.y = fmaf(f.y, w[j], acc.y);
                    acc.z = fmaf(f.z, w[j], acc.z);
                    acc.w = fmaf(f.w, w[j], acc.w);
                }
            }
        }
    }

    float4 bv = ((const float4*)b)[q];
    float4 y;
    y.x = fmaxf(fmaf(acc.x, di, bv.x), 0.f);
    y.y = fmaxf(fmaf(acc.y, di, bv.y), 0.f);
    y.z = fmaxf(fmaf(acc.z, di, bv.z), 0.f);
    y.w = fmaxf(fmaf(acc.w, di, bv.w), 0.f);
    ((float4*)g_out)[(size_t)node * 16 + q] = y;

    __shared__ float sY[16][HH + 4];
    __shared__ int   sB[16];
    sY[grp][q*4+0] = y.x;
    sY[grp][q*4+1] = y.y;
    sY[grp][q*4+2] = y.z;
    sY[grp][q*4+3] = y.w;
    if (q == 0) sB[grp] = batch[node];
    __syncthreads();

    if (tid < HH) {
        int c = tid;
        float s = 0.f, s2 = 0.f, pacc = 0.f;
        int curg = sB[0];
#pragma unroll
        for (int g2 = 0; g2 < 16; g2++) {
            float v = sY[g2][c];
            s += v;
            s2 = fmaf(v, v, s2);
            int gi = sB[g2];
            if (gi != curg) {
                atomicAdd(&pool[(size_t)curg * 192 + c], pacc);
                curg = gi; pacc = 0.f;
            }
            pacc += v;
        }
        atomicAdd(&pool[(size_t)curg * 192 + c], pacc);
        atomicAdd(&g_sum  [layer * HH + c], s);
        atomicAdd(&g_sumsq[layer * HH + c], s2);
    }
}

// ---- finale: BN params (all 3 layers) + pool fixups + final h output ----
__global__ __launch_bounds__(256) void k_fin(float* __restrict__ out,
                                             float* __restrict__ outh,
                                             const float* __restrict__ gam0,
                                             const float* __restrict__ bet0,
                                             const float* __restrict__ gam1,
                                             const float* __restrict__ bet1,
                                             const float* __restrict__ gam2,
                                             const float* __restrict__ bet2)
{
    __shared__ float sSc[3 * HH], sDc[3 * HH];
    int t = threadIdx.x;
    pdl_wait();   // g_sum/g_sumsq/pool raw from final k_agg

    if (t < 3 * HH) {
        int l = t >> 6, c = t & 63;
        const float* ga = (l == 0) ? gam0 : (l == 1) ? gam1 : gam2;
        const float* be = (l == 0) ? bet0 : (l == 1) ? bet1 : bet2;
        float m   = g_sum  [t] * (1.0f / NN);
        float var = g_sumsq[t] * (1.0f / NN) - m * m;
        float r = rsqrtf(var + BN_EPS);
        float sc = ga[c] * r;
        sSc[t] = sc;
        sDc[t] = be[c] - m * sc;
    }
    __syncthreads();

    int idx = blockIdx.x * 256 + t;

    if (idx < GG * HH) {
        int gph = idx >> 6, c = idx & 63;
        float cntf = (float)g_cnt[gph];
#pragma unroll
        for (int l = 0; l < 3; l++) {
            float* p = out + (size_t)gph * 192 + l * 64 + c;
            float raw = *p;
            *p = sSc[l * HH + c] * raw + cntf * sDc[l * HH + c];
        }
    }

    if (idx < NN * 16) {
        float4 v = ((const float4*)g_out)[idx];
        int c = (idx & 15) * 4;
        v.x = v.x * sSc[2*HH + c]     + sDc[2*HH + c];
        v.y = v.y * sSc[2*HH + c + 1] + sDc[2*HH + c + 1];
        v.z = v.z * sSc[2*HH + c + 2] + sDc[2*HH + c + 2];
        v.w = v.w * sSc[2*HH + c + 3] + sDc[2*HH + c + 3];
        ((float4*)outh)[idx] = v;
    }
}

// ---------------- PDL launch helper ----------------
template <typename F, typename... Args>
static inline void launch_pdl(F* f, dim3 grid, dim3 block, cudaStream_t st, Args... args)
{
    cudaLaunchConfig_t cfg = {};
    cfg.gridDim = grid;
    cfg.blockDim = block;
    cfg.dynamicSmemBytes = 0;
    cfg.stream = st;
    cudaLaunchAttribute at[1];
    at[0].id = cudaLaunchAttributeProgrammaticStreamSerialization;
    at[0].val.programmaticStreamSerializationAllowed = 1;
    cfg.attrs = at;
    cfg.numAttrs = 1;
    cudaLaunchKernelEx(&cfg, f, args...);
}

// ---------------- host launcher ----------------
extern "C" void kernel_launch(void* const* d_in, const int* in_sizes, int n_in,
                              void* d_out, int out_size)
{
    const float* x     = (const float*)d_in[0];
    const int*   eidx  = (const int*)  d_in[1];
    const int*   batch = (const int*)  d_in[2];
    const int*   src   = eidx;
    const int*   dst   = eidx + EE;

    const float* W[3]   = { (const float*)d_in[3],  (const float*)d_in[7],  (const float*)d_in[11] };
    const float* b[3]   = { (const float*)d_in[4],  (const float*)d_in[8],  (const float*)d_in[12] };
    const float* gam[3] = { (const float*)d_in[5],  (const float*)d_in[9],  (const float*)d_in[13] };
    const float* bet[3] = { (const float*)d_in[6],  (const float*)d_in[10], (const float*)d_in[14] };

    float* out = (float*)d_out;

    float* d_relu;
    cudaGetSymbolAddress((void**)&d_relu, g_out);

    // lazily create side stream + events on the first (non-captured) call
    static cudaStream_t s2 = nullptr;
    static cudaEvent_t  evFork = nullptr, evJoin = nullptr;
    if (!s2) {
        cudaStreamCreateWithFlags(&s2, cudaStreamNonBlocking);
        cudaEventCreateWithFlags(&evFork, cudaEventDisableTiming);
        cudaEventCreateWithFlags(&evJoin, cudaEventDisableTiming);
    }

    // init, then fork: layer-0 GEMM (identity BN fold) on s2
    k_init<<<(NN + 255) / 256, 256>>>(out);
    cudaEventRecord(evFork, 0);
    cudaStreamWaitEvent(s2, evFork, 0);
    k_gemm<<<(NN + 127) / 128, 128, 0, s2>>>(x, W[0], (const float*)nullptr,
                                             (const float*)nullptr, 0);
    cudaEventRecord(evJoin, s2);

    // CSR build on the main stream (overlaps gemm0), PDL-chained
    launch_pdl(k_deg,   dim3((EE / 4 + 255) / 256), dim3(256), (cudaStream_t)0, dst);
    launch_pdl(k_scan1, dim3(NBLK), dim3(SCAN_B), (cudaStream_t)0);
    launch_pdl(k_scan3, dim3((NN + 255) / 256), dim3(256), (cudaStream_t)0, batch);
    launch_pdl(k_bucket,dim3((EE / 4 + 255) / 256), dim3(256), (cudaStream_t)0, src, dst);
    cudaStreamWaitEvent(0, evJoin, 0);

    for (int l = 0; l < 3; l++) {
        if (l > 0)
            launch_pdl(k_gemm, dim3((NN + 127) / 128), dim3(128), (cudaStream_t)0,
                       (const float*)d_relu, W[l], gam[l - 1], bet[l - 1], l - 1);
        launch_pdl(k_agg, dim3(NN / 16), dim3(256), (cudaStream_t)0,
                   b[l], batch, out + l * 64, l);
    }
    launch_pdl(k_fin, dim3((NN * 16 + 255) / 256), dim3(256), (cudaStream_t)0,
               out, out + (size_t)GG * 192,
               gam[0], bet[0], gam[1], bet[1], gam[2], bet[2]);
}